// round 2
// baseline (speedup 1.0000x reference)
#include <cuda_runtime.h>

// RegionPartitioner: extract 15x15 overlapping 64x64 regions (stride 32)
// from an edge-padded (8,4,500,500) fp32 tensor.
// out[b, r, c, i, j] = x[b, c, min(ri*32+i, 499), min(rj*32+j, 499)]
//   where r = ri*15 + rj.
// Output: (8, 225, 4, 64, 64) fp32 = 29,491,200 floats.

namespace {
constexpr int B  = 8;
constexpr int C  = 4;
constexpr int H  = 500;
constexpr int W  = 500;
constexpr int RS = 64;     // region size
constexpr int ST = 32;     // step
constexpr int NR = 15;     // regions per dim
constexpr int R  = NR * NR;   // 225 regions
constexpr int OUT_FLOATS = B * R * C * RS * RS;   // 29,491,200
constexpr int OUT_VEC4   = OUT_FLOATS / 4;        // 7,372,800
}  // namespace

__global__ __launch_bounds__(256)
void region_partition_kernel(const float* __restrict__ x,
                             float4* __restrict__ out) {
    int v = blockIdx.x * blockDim.x + threadIdx.x;
    if (v >= OUT_VEC4) return;

    // Decode output coordinate from linear float4 index.
    // Layout: (((b*R + r)*C + c)*RS + i)*RS + j, j in groups of 4.
    int j4 = v & 15;            // float4 index within row (j = j4*4)
    int i  = (v >> 4) & 63;     // row within region
    int c  = (v >> 10) & 3;     // channel
    int rr = v >> 12;           // b*R + r
    int r  = rr % R;
    int b  = rr / R;
    int ri = r / NR;
    int rj = r % NR;

    int row  = ri * ST + i;
    if (row > H - 1) row = H - 1;           // edge clamp (only ri==14)
    int col0 = rj * ST + j4 * 4;

    const float* src = x + ((long long)(b * C + c) * H + row) * W;

    float4 val;
    if (col0 + 3 <= W - 1) {
        // Fast path: 500*4 bytes row stride and col0%4==0 -> 16B aligned.
        val = *reinterpret_cast<const float4*>(src + col0);
    } else {
        // Edge clamp on columns (only rj==14, cols >= 500).
        int c0 = col0;     if (c0 > W - 1) c0 = W - 1;
        int c1 = col0 + 1; if (c1 > W - 1) c1 = W - 1;
        int c2 = col0 + 2; if (c2 > W - 1) c2 = W - 1;
        int c3 = col0 + 3; if (c3 > W - 1) c3 = W - 1;
        val.x = src[c0];
        val.y = src[c1];
        val.z = src[c2];
        val.w = src[c3];
    }

    out[v] = val;
}

extern "C" void kernel_launch(void* const* d_in, const int* in_sizes, int n_in,
                              void* d_out, int out_size) {
    const float* x = (const float*)d_in[0];
    float4* out = (float4*)d_out;

    constexpr int threads = 256;
    constexpr int blocks  = (OUT_VEC4 + threads - 1) / threads;  // 28800
    region_partition_kernel<<<blocks, threads>>>(x, out);
}

// round 4
// speedup vs baseline: 1.2766x; 1.2766x over previous
#include <cuda_runtime.h>

// RegionPartitioner: extract 15x15 overlapping 64x64 regions (stride 32)
// from an edge-padded (8,4,500,500) fp32 tensor.
// out[b, r, c, i, j] = x[b, c, min(ri*32+i, 499), min(rj*32+j, 499)],
//   r = ri*15 + rj.  Output: (8, 225, 4, 64, 64) fp32.
//
// Grid: (C=4, B*R=1800). Block: 256 threads.
// Each thread produces 4 consecutive region-rows worth of one float4 column
// (64 B out), loading all 4 float4 first (MLP=4) then storing.

namespace {
constexpr int B  = 8;
constexpr int C  = 4;
constexpr int H  = 500;
constexpr int W  = 500;
constexpr int RS = 64;
constexpr int ST = 32;
constexpr int NR = 15;
constexpr int R  = NR * NR;   // 225
}  // namespace

__global__ __launch_bounds__(256)
void region_partition_kernel(const float* __restrict__ x,
                             float4* __restrict__ out) {
    const int rr = blockIdx.y;        // b*R + r   (0..1799)
    const int c  = blockIdx.x;        // 0..3
    const int r  = rr % R;
    const int b  = rr / R;
    const int ri = r / NR;
    const int rj = r % NR;

    const int t  = threadIdx.x;
    const int j4 = t & 15;            // float4 column within region row
    const int i0 = (t >> 4) << 2;     // starting region row: 0,4,...,60

    const int col0    = rj * ST + j4 * 4;
    const bool colfast = (col0 + 3 <= W - 1);

    const float* srcbase = x + (long long)(b * C + c) * H * W;

    // Gather 4 rows first for MLP=4.
    float4 vals[4];
#pragma unroll
    for (int k = 0; k < 4; k++) {
        int row = ri * ST + i0 + k;
        if (row > H - 1) row = H - 1;                 // edge clamp (ri==14 only)
        const float* src = srcbase + row * W;
        if (colfast) {
            vals[k] = *reinterpret_cast<const float4*>(src + col0);
        } else {
            int c0 = min(col0,     W - 1);
            int c1 = min(col0 + 1, W - 1);
            int c2 = min(col0 + 2, W - 1);
            int c3 = min(col0 + 3, W - 1);
            vals[k].x = src[c0];
            vals[k].y = src[c1];
            vals[k].z = src[c2];
            vals[k].w = src[c3];
        }
    }

    // Coalesced stores: within each k, 16 consecutive threads write 256B runs.
    float4* dst = out + ((((long long)rr * C + c) * RS + i0) * (RS / 4) + j4);
#pragma unroll
    for (int k = 0; k < 4; k++) {
        dst[k * (RS / 4)] = vals[k];
    }
}

extern "C" void kernel_launch(void* const* d_in, const int* in_sizes, int n_in,
                              void* d_out, int out_size) {
    const float* x = (const float*)d_in[0];
    float4* out = (float4*)d_out;

    dim3 grid(C, B * R);   // (4, 1800)
    region_partition_kernel<<<grid, 256>>>(x, out);
}